// round 16
// baseline (speedup 1.0000x reference)
#include <cuda_runtime.h>
#include <cuda_fp16.h>
#include <cstdint>
#include <cstddef>

// Problem constants
#define BB    4
#define NN    4096
#define DIN   256
#define DOUT  128
#define COS_EPS    0.001f
#define THRESHOLD  0.1f
#define LEAKY      0.01f
#define FIX_WIN    2e-4f

// ---------------------------------------------------------------------------
// Scratch (static device globals; no allocations allowed)
// ---------------------------------------------------------------------------
__device__ float          g_h[BB * NN * DOUT];     // fp32 h (exact recompute)
__device__ __half         g_hf[BB * NN * DOUT];    // fp16 h (gram operand)
__device__ float          g_norm[BB * NN];
__device__ float          g_rnorm[BB * NN];

__device__ __forceinline__ uint32_t smem_u32(const void* p) {
    uint32_t a;
    asm("{ .reg .u64 t; cvta.to.shared.u64 t, %1; cvt.u32.u64 %0, t; }"
        : "=r"(a) : "l"(p));
    return a;
}

__device__ __forceinline__ void ldsm_x4(uint32_t* r, uint32_t addr) {
    asm volatile("ldmatrix.sync.aligned.m8n8.x4.shared.b16 {%0,%1,%2,%3}, [%4];"
                 : "=r"(r[0]), "=r"(r[1]), "=r"(r[2]), "=r"(r[3]) : "r"(addr));
}
__device__ __forceinline__ void mma_f16(float* d, const uint32_t* a, const uint32_t* b) {
    asm volatile(
        "mma.sync.aligned.m16n8k16.row.col.f32.f16.f16.f32 "
        "{%0,%1,%2,%3}, {%4,%5,%6,%7}, {%8,%9}, {%0,%1,%2,%3};"
        : "+f"(d[0]), "+f"(d[1]), "+f"(d[2]), "+f"(d[3])
        : "r"(a[0]), "r"(a[1]), "r"(a[2]), "r"(a[3]), "r"(b[0]), "r"(b[1]));
}

extern __shared__ char smem_raw[];

// ---------------------------------------------------------------------------
// Kernel A: h = leaky_relu(z @ W) + fused row norms + fp16 cast.
// At the fp32 FMA floor (~31.5us); 64x128 tile, 128 threads, 8x8/thread.
// ---------------------------------------------------------------------------
#define Z_ROWLEN 68
#define GEMM1_SMEM ((64 * Z_ROWLEN + 64 * DOUT) * 4)
__global__ void __launch_bounds__(128, 2)
gemm1_kernel(const float* __restrict__ z, const float* __restrict__ W)
{
    float* smem = (float*)smem_raw;
    float* Zs = smem;                       // [64 k][68]  (transposed [k][m])
    float* Ws = smem + 64 * Z_ROWLEN;       // [64 k][128]

    const int m0  = blockIdx.x * 64;
    const int tid = threadIdx.x;
    const int tm  = tid >> 4;               // 0..7
    const int tn  = tid & 15;               // 0..15

    float acc[8][8];
#pragma unroll
    for (int i = 0; i < 8; i++)
#pragma unroll
        for (int j = 0; j < 8; j++) acc[i][j] = 0.f;

    for (int k0 = 0; k0 < DIN; k0 += 64) {
#pragma unroll
        for (int t = 0; t < 8; t++) {
            int idx = tid + t * 128;
            int r   = idx >> 4;
            int kk  = (idx & 15) << 2;
            float4 v = *(const float4*)(z + (size_t)(m0 + r) * DIN + k0 + kk);
            Zs[(kk + 0) * Z_ROWLEN + r] = v.x;
            Zs[(kk + 1) * Z_ROWLEN + r] = v.y;
            Zs[(kk + 2) * Z_ROWLEN + r] = v.z;
            Zs[(kk + 3) * Z_ROWLEN + r] = v.w;
        }
#pragma unroll
        for (int t = 0; t < 16; t++) {
            int idx = tid + t * 128;
            int kk  = idx >> 5;
            int n4  = (idx & 31) << 2;
            float4 v = *(const float4*)(W + (size_t)(k0 + kk) * DOUT + n4);
            *(float4*)&Ws[kk * DOUT + n4] = v;
        }
        __syncthreads();

#pragma unroll 8
        for (int k = 0; k < 64; k++) {
            float a[8], b[8];
            *(float4*)(a)     = *(float4*)&Zs[k * Z_ROWLEN + tm * 8];
            *(float4*)(a + 4) = *(float4*)&Zs[k * Z_ROWLEN + tm * 8 + 4];
            *(float4*)(b)     = *(float4*)&Ws[k * DOUT + tn * 8];
            *(float4*)(b + 4) = *(float4*)&Ws[k * DOUT + tn * 8 + 4];
#pragma unroll
            for (int i = 0; i < 8; i++)
#pragma unroll
                for (int j = 0; j < 8; j++)
                    acc[i][j] += a[i] * b[j];
        }
        __syncthreads();
    }

#pragma unroll
    for (int i = 0; i < 8; i++) {
        int row = m0 + tm * 8 + i;
        float vv[8];
        float ss = 0.f;
#pragma unroll
        for (int j = 0; j < 8; j++) {
            float x = acc[i][j];
            float v = (x > 0.f) ? x : LEAKY * x;
            vv[j] = v;
            ss += v * v;
        }
#pragma unroll
        for (int off = 1; off < 16; off <<= 1)
            ss += __shfl_xor_sync(0xFFFFFFFFu, ss, off);

        float* dst = g_h + (size_t)row * DOUT + tn * 8;
        *(float4*)(dst)     = make_float4(vv[0], vv[1], vv[2], vv[3]);
        *(float4*)(dst + 4) = make_float4(vv[4], vv[5], vv[6], vv[7]);

        union { __half2 h2[4]; uint4 u; } ph;
        ph.h2[0] = __floats2half2_rn(vv[0], vv[1]);
        ph.h2[1] = __floats2half2_rn(vv[2], vv[3]);
        ph.h2[2] = __floats2half2_rn(vv[4], vv[5]);
        ph.h2[3] = __floats2half2_rn(vv[6], vv[7]);
        *(uint4*)(g_hf + (size_t)row * DOUT + tn * 8) = ph.u;

        if (tn == 0) {
            float n = sqrtf(ss);
            g_norm[row]  = n;
            g_rnorm[row] = (n > 0.f) ? (1.0f / n) : 0.f;
        }
    }
}

// ---------------------------------------------------------------------------
// Kernel C: fp16 single-pass Gram, 256 threads, 8 warps (2m x 4n),
// warp tile 64x32 (6 ldsm per 16 MMAs = 0.375 ldsm/MMA -> smem crossbar
// no longer co-binding with HMMA). No smem stage:
//  - Main tile: st.v2 from registers (32B sectors).
//  - Mirror tile: scalar STG.32; lanes w/ equal (lane&3) hold consecutive r
//    -> full 32B sectors.
//  - Near-threshold: smem queue; drain (1 warp/entry, exact fp32 dot from
//    L2-resident g_h) patches both gmem locations.
// K=128 smem-resident, __launch_bounds__(256, 2). Triangular grid [0,528).
// ---------------------------------------------------------------------------
#define OFF_A       0
#define OFF_B       32768
#define OFF_PARAMS  65536
#define OFF_NA      (OFF_PARAMS)
#define OFF_NB      (OFF_PARAMS + 512)
#define OFF_RNA     (OFF_PARAMS + 1024)
#define OFF_RNB     (OFF_PARAMS + 1536)
#define OFF_QCNT    (OFF_PARAMS + 2048)
#define OFF_QUEUE   (OFF_PARAMS + 2064)
#define QCAP        2048
#define GRAM_SMEM   (OFF_QUEUE + QCAP * 4)

__global__ void __launch_bounds__(256, 2)
gram_f16_kernel(float* __restrict__ out)
{
    // Triangular tile index -> (bx, by) with by >= bx
    int tt = blockIdx.x;
    int by = (int)((sqrtf(8.f * tt + 1.f) - 1.f) * 0.5f);
    while ((by + 1) * (by + 2) / 2 <= tt) by++;
    while (by * (by + 1) / 2 > tt) by--;
    const int bx = tt - by * (by + 1) / 2;
    const int b  = blockIdx.y;
    const bool offdiag = (bx != by);

    char* smem = smem_raw;
    const uint32_t sb = smem_u32(smem);
    const int tid  = threadIdx.x;
    const int lane = tid & 31;
    const int wid  = tid >> 5;
    const int warp_m = wid >> 2;          // 0..1 (64 rows each)
    const int warp_n = wid & 3;           // 0..3 (32 cols each)

    const int i0 = bx * 128, j0 = by * 128;
    const size_t hbase = (size_t)b * NN * DOUT;
    const size_t nbase = (size_t)b * NN;
    float* outb = out + (size_t)b * NN * NN;

    // ---- Load fp16 operand tiles (32KB each), XOR-swizzled 256B rows ----
    {
        const uint4* srcA = (const uint4*)(g_hf + hbase + (size_t)i0 * DOUT);
        const uint4* srcB = (const uint4*)(g_hf + hbase + (size_t)j0 * DOUT);
#pragma unroll
        for (int t = 0; t < 8; t++) {
            int idx = tid + t * 256;            // 0..2047 16B chunks
            int row = idx >> 4;                 // 16 chunks per 256B row
            int c   = idx & 15;
            uint32_t off = (uint32_t)(row * 256) + (uint32_t)((c ^ (row & 7)) << 4);
            *(uint4*)(smem + OFF_A + off) = srcA[idx];
            *(uint4*)(smem + OFF_B + off) = srcB[idx];
        }
        if (tid < 128) {
            ((float*)(smem + OFF_NA))[tid]  = g_norm[nbase + i0 + tid];
            ((float*)(smem + OFF_NB))[tid]  = g_norm[nbase + j0 + tid];
            ((float*)(smem + OFF_RNA))[tid] = g_rnorm[nbase + i0 + tid];
            ((float*)(smem + OFF_RNB))[tid] = g_rnorm[nbase + j0 + tid];
        }
        if (tid == 0) *(int*)(smem + OFF_QCNT) = 0;
    }
    __syncthreads();

    // ---- MMA mainloop: single pass, 8 ksteps of 16 ----
    float acc[4][4][4];                    // [mf][nf(q*2+e)][frag]
#pragma unroll
    for (int mf = 0; mf < 4; mf++)
#pragma unroll
        for (int nf = 0; nf < 4; nf++)
#pragma unroll
            for (int r = 0; r < 4; r++) acc[mf][nf][r] = 0.f;

    const uint32_t abase = sb + OFF_A;
    const uint32_t bbase = sb + OFF_B;

    // A fragment: rows warp_m*64 + mf*16 + (lane&15), k-half = lane>>4
    const int a_row  = warp_m * 64 + (lane & 15);
    const int a_ksel = lane >> 4;
    const int a_swz  = a_row & 7;          // +16 multiples keep low 3 bits
    uint32_t a_rb[4];
#pragma unroll
    for (int mf = 0; mf < 4; mf++) a_rb[mf] = (uint32_t)((a_row + mf * 16) * 256);
    // B fragment (non-trans): n-rows warp_n*32 + q*16 + (lane&7)+((lane>>4)<<3)
    const int b_row  = warp_n * 32 + (lane & 7) + ((lane >> 4) << 3);
    const int b_ksel = (lane >> 3) & 1;
    const int b_swz  = b_row & 7;
    const uint32_t b_rb0 = (uint32_t)(b_row * 256);
    const uint32_t b_rb1 = (uint32_t)((b_row + 16) * 256);

#pragma unroll
    for (int s = 0; s < 8; s++) {
        uint32_t abuf[4][4], bbuf[2][4];
        uint32_t ac = (uint32_t)((s * 2 + a_ksel) ^ a_swz) << 4;
        uint32_t bc = (uint32_t)((s * 2 + b_ksel) ^ b_swz) << 4;
#pragma unroll
        for (int mf = 0; mf < 4; mf++)
            ldsm_x4(abuf[mf], abase + a_rb[mf] + ac);
        ldsm_x4(bbuf[0], bbase + b_rb0 + bc);
        ldsm_x4(bbuf[1], bbase + b_rb1 + bc);
#pragma unroll
        for (int mf = 0; mf < 4; mf++)
#pragma unroll
            for (int q = 0; q < 2; q++) {
                mma_f16(acc[mf][q * 2 + 0], abuf[mf], &bbuf[q][0]);
                mma_f16(acc[mf][q * 2 + 1], abuf[mf], &bbuf[q][2]);
            }
    }

    // ---- Epilogue: cosine + threshold; direct main + mirror stores ----
    {
        const float* nA  = (const float*)(smem + OFF_NA);
        const float* nB  = (const float*)(smem + OFF_NB);
        const float* rnA = (const float*)(smem + OFF_RNA);
        const float* rnB = (const float*)(smem + OFF_RNB);
        int*   qcnt  = (int*)(smem + OFF_QCNT);
        int*   queue = (int*)(smem + OFF_QUEUE);

#pragma unroll
        for (int mf = 0; mf < 4; mf++) {
            int r_lo = warp_m * 64 + mf * 16 + (lane >> 2);
#pragma unroll
            for (int half = 0; half < 2; half++) {
                int r = r_lo + half * 8;
                float nm = nA[r], rnm = rnA[r];
#pragma unroll
                for (int nf = 0; nf < 4; nf++) {
                    int c0 = warp_n * 32 + nf * 8 + (lane & 3) * 2;
                    float res[2];
#pragma unroll
                    for (int e = 0; e < 2; e++) {
                        int c = c0 + e;
                        float dot = acc[mf][nf][half * 2 + e];
                        float t = nm * nB[c];
                        float f = (t >= COS_EPS) ? (rnm * rnB[c]) : (1.0f / COS_EPS);
                        float v = fabsf(dot) * f;
                        if (fabsf(v - THRESHOLD) < FIX_WIN) {
                            int qi = atomicAdd(qcnt, 1);
                            if (qi < QCAP) queue[qi] = (r << 8) | c;
                        }
                        res[e] = (v > THRESHOLD) ? v : 0.f;
                        if (offdiag)
                            outb[(size_t)(j0 + c) * NN + (i0 + r)] = res[e];
                    }
                    *(float2*)(outb + (size_t)(i0 + r) * NN + (j0 + c0)) =
                        make_float2(res[0], res[1]);
                }
            }
        }
    }
    __syncthreads();   // all approx stores + queue entries visible

    // ---- Drain fixup queue: one warp per entry, exact fp32 dot from g_h ----
    {
        const float* nA = (const float*)(smem + OFF_NA);
        const float* nB = (const float*)(smem + OFF_NB);
        int qn = *(int*)(smem + OFF_QCNT);
        if (qn > QCAP) qn = QCAP;
        const int* queue = (const int*)(smem + OFF_QUEUE);

        for (int q = wid; q < qn; q += 8) {
            int rc = queue[q];
            int r = rc >> 8, c = rc & 255;
            const float4* hi4 = (const float4*)(g_h + hbase + (size_t)(i0 + r) * DOUT);
            const float4* hj4 = (const float4*)(g_h + hbase + (size_t)(j0 + c) * DOUT);
            float4 a = hi4[lane], bb = hj4[lane];
            float d = a.x * bb.x + a.y * bb.y + a.z * bb.z + a.w * bb.w;
#pragma unroll
            for (int off = 16; off > 0; off >>= 1)
                d += __shfl_xor_sync(0xFFFFFFFFu, d, off);
            if (lane == 0) {
                float denom = fmaxf(nA[r] * nB[c], COS_EPS);
                float v = fabsf(d) / denom;
                float res = (v > THRESHOLD) ? v : 0.f;
                outb[(size_t)(i0 + r) * NN + (j0 + c)] = res;        // main
                if (offdiag)
                    outb[(size_t)(j0 + c) * NN + (i0 + r)] = res;    // mirror
            }
        }
    }
}

// ---------------------------------------------------------------------------
extern "C" void kernel_launch(void* const* d_in, const int* in_sizes, int n_in,
                              void* d_out, int out_size)
{
    (void)in_sizes; (void)n_in; (void)out_size;
    const float* z = (const float*)d_in[0];
    const float* W = (const float*)d_in[1];
    float* out = (float*)d_out;

    static bool attrs_set = false;
    if (!attrs_set) {
        cudaFuncSetAttribute(gemm1_kernel, cudaFuncAttributeMaxDynamicSharedMemorySize, GEMM1_SMEM);
        cudaFuncSetAttribute(gram_f16_kernel, cudaFuncAttributeMaxDynamicSharedMemorySize, GRAM_SMEM);
        attrs_set = true;
    }

    gemm1_kernel<<<BB * NN / 64, 128, GEMM1_SMEM>>>(z, W);
    dim3 grid(528, BB);
    gram_f16_kernel<<<grid, 256, GRAM_SMEM>>>(out);
}

// round 17
// speedup vs baseline: 1.0883x; 1.0883x over previous
#include <cuda_runtime.h>
#include <cuda_fp16.h>
#include <cstdint>
#include <cstddef>

// Problem constants
#define BB    4
#define NN    4096
#define DIN   256
#define DOUT  128
#define COS_EPS    0.001f
#define THRESHOLD  0.1f
#define LEAKY      0.01f
#define FIX_WIN    2e-4f

// ---------------------------------------------------------------------------
// Scratch (static device globals; no allocations allowed)
// ---------------------------------------------------------------------------
__device__ float          g_h[BB * NN * DOUT];     // fp32 h (exact recompute)
__device__ __half         g_hf[BB * NN * DOUT];    // fp16 h (gram operand)
__device__ float          g_norm[BB * NN];
__device__ float          g_rnorm[BB * NN];

__device__ __forceinline__ uint32_t smem_u32(const void* p) {
    uint32_t a;
    asm("{ .reg .u64 t; cvta.to.shared.u64 t, %1; cvt.u32.u64 %0, t; }"
        : "=r"(a) : "l"(p));
    return a;
}

__device__ __forceinline__ void ldsm_x4(uint32_t* r, uint32_t addr) {
    asm volatile("ldmatrix.sync.aligned.m8n8.x4.shared.b16 {%0,%1,%2,%3}, [%4];"
                 : "=r"(r[0]), "=r"(r[1]), "=r"(r[2]), "=r"(r[3]) : "r"(addr));
}
__device__ __forceinline__ void mma_f16(float* d, const uint32_t* a, const uint32_t* b) {
    asm volatile(
        "mma.sync.aligned.m16n8k16.row.col.f32.f16.f16.f32 "
        "{%0,%1,%2,%3}, {%4,%5,%6,%7}, {%8,%9}, {%0,%1,%2,%3};"
        : "+f"(d[0]), "+f"(d[1]), "+f"(d[2]), "+f"(d[3])
        : "r"(a[0]), "r"(a[1]), "r"(a[2]), "r"(a[3]), "r"(b[0]), "r"(b[1]));
}

extern __shared__ char smem_raw[];

// ---------------------------------------------------------------------------
// Kernel A: h = leaky_relu(z @ W) + fused row norms + fp16 cast.
// At the fp32 FMA floor (~31.5us); 64x128 tile, 128 threads, 8x8/thread.
// ---------------------------------------------------------------------------
#define Z_ROWLEN 68
#define GEMM1_SMEM ((64 * Z_ROWLEN + 64 * DOUT) * 4)
__global__ void __launch_bounds__(128, 2)
gemm1_kernel(const float* __restrict__ z, const float* __restrict__ W)
{
    float* smem = (float*)smem_raw;
    float* Zs = smem;                       // [64 k][68]  (transposed [k][m])
    float* Ws = smem + 64 * Z_ROWLEN;       // [64 k][128]

    const int m0  = blockIdx.x * 64;
    const int tid = threadIdx.x;
    const int tm  = tid >> 4;               // 0..7
    const int tn  = tid & 15;               // 0..15

    float acc[8][8];
#pragma unroll
    for (int i = 0; i < 8; i++)
#pragma unroll
        for (int j = 0; j < 8; j++) acc[i][j] = 0.f;

    for (int k0 = 0; k0 < DIN; k0 += 64) {
#pragma unroll
        for (int t = 0; t < 8; t++) {
            int idx = tid + t * 128;
            int r   = idx >> 4;
            int kk  = (idx & 15) << 2;
            float4 v = *(const float4*)(z + (size_t)(m0 + r) * DIN + k0 + kk);
            Zs[(kk + 0) * Z_ROWLEN + r] = v.x;
            Zs[(kk + 1) * Z_ROWLEN + r] = v.y;
            Zs[(kk + 2) * Z_ROWLEN + r] = v.z;
            Zs[(kk + 3) * Z_ROWLEN + r] = v.w;
        }
#pragma unroll
        for (int t = 0; t < 16; t++) {
            int idx = tid + t * 128;
            int kk  = idx >> 5;
            int n4  = (idx & 31) << 2;
            float4 v = *(const float4*)(W + (size_t)(k0 + kk) * DOUT + n4);
            *(float4*)&Ws[kk * DOUT + n4] = v;
        }
        __syncthreads();

#pragma unroll 8
        for (int k = 0; k < 64; k++) {
            float a[8], b[8];
            *(float4*)(a)     = *(float4*)&Zs[k * Z_ROWLEN + tm * 8];
            *(float4*)(a + 4) = *(float4*)&Zs[k * Z_ROWLEN + tm * 8 + 4];
            *(float4*)(b)     = *(float4*)&Ws[k * DOUT + tn * 8];
            *(float4*)(b + 4) = *(float4*)&Ws[k * DOUT + tn * 8 + 4];
#pragma unroll
            for (int i = 0; i < 8; i++)
#pragma unroll
                for (int j = 0; j < 8; j++)
                    acc[i][j] += a[i] * b[j];
        }
        __syncthreads();
    }

#pragma unroll
    for (int i = 0; i < 8; i++) {
        int row = m0 + tm * 8 + i;
        float vv[8];
        float ss = 0.f;
#pragma unroll
        for (int j = 0; j < 8; j++) {
            float x = acc[i][j];
            float v = (x > 0.f) ? x : LEAKY * x;
            vv[j] = v;
            ss += v * v;
        }
#pragma unroll
        for (int off = 1; off < 16; off <<= 1)
            ss += __shfl_xor_sync(0xFFFFFFFFu, ss, off);

        float* dst = g_h + (size_t)row * DOUT + tn * 8;
        *(float4*)(dst)     = make_float4(vv[0], vv[1], vv[2], vv[3]);
        *(float4*)(dst + 4) = make_float4(vv[4], vv[5], vv[6], vv[7]);

        union { __half2 h2[4]; uint4 u; } ph;
        ph.h2[0] = __floats2half2_rn(vv[0], vv[1]);
        ph.h2[1] = __floats2half2_rn(vv[2], vv[3]);
        ph.h2[2] = __floats2half2_rn(vv[4], vv[5]);
        ph.h2[3] = __floats2half2_rn(vv[6], vv[7]);
        *(uint4*)(g_hf + (size_t)row * DOUT + tn * 8) = ph.u;

        if (tn == 0) {
            float n = sqrtf(ss);
            g_norm[row]  = n;
            g_rnorm[row] = (n > 0.f) ? (1.0f / n) : 0.f;
        }
    }
}

// ---------------------------------------------------------------------------
// Kernel C: fp16 single-pass Gram (R15 config) + STREAMING output stores
// (__stcs evict-first: the 268MB write-once output no longer evicts the
// L2-resident g_hf operand tiles / g_h fixup rows).
//  - Main tile: __stcs float2 from registers (32B sectors).
//  - Mirror tile: __stcs scalar; lanes w/ equal (lane&3) hold consecutive r
//    -> full 32B sectors.
//  - Near-threshold: smem queue; drain (1 warp/entry, exact fp32 dot from
//    L2-resident g_h) patches both gmem locations.
// 512 threads, 16 warps (4m x 4n), warp tile 32x32, K=128 smem-resident,
// __launch_bounds__(512, 2). Triangular grid: blockIdx.x in [0,528).
// ---------------------------------------------------------------------------
#define OFF_A       0
#define OFF_B       32768
#define OFF_PARAMS  65536
#define OFF_NA      (OFF_PARAMS)
#define OFF_NB      (OFF_PARAMS + 512)
#define OFF_RNA     (OFF_PARAMS + 1024)
#define OFF_RNB     (OFF_PARAMS + 1536)
#define OFF_QCNT    (OFF_PARAMS + 2048)
#define OFF_QUEUE   (OFF_PARAMS + 2064)
#define QCAP        2048
#define GRAM_SMEM   (OFF_QUEUE + QCAP * 4)

__global__ void __launch_bounds__(512, 2)
gram_f16_kernel(float* __restrict__ out)
{
    // Triangular tile index -> (bx, by) with by >= bx
    int tt = blockIdx.x;
    int by = (int)((sqrtf(8.f * tt + 1.f) - 1.f) * 0.5f);
    while ((by + 1) * (by + 2) / 2 <= tt) by++;
    while (by * (by + 1) / 2 > tt) by--;
    const int bx = tt - by * (by + 1) / 2;
    const int b  = blockIdx.y;
    const bool offdiag = (bx != by);

    char* smem = smem_raw;
    const uint32_t sb = smem_u32(smem);
    const int tid  = threadIdx.x;
    const int lane = tid & 31;
    const int wid  = tid >> 5;
    const int warp_m = wid >> 2;
    const int warp_n = wid & 3;

    const int i0 = bx * 128, j0 = by * 128;
    const size_t hbase = (size_t)b * NN * DOUT;
    const size_t nbase = (size_t)b * NN;
    float* outb = out + (size_t)b * NN * NN;

    // ---- Load fp16 operand tiles (32KB each), XOR-swizzled 256B rows ----
    {
        const uint4* srcA = (const uint4*)(g_hf + hbase + (size_t)i0 * DOUT);
        const uint4* srcB = (const uint4*)(g_hf + hbase + (size_t)j0 * DOUT);
#pragma unroll
        for (int t = 0; t < 4; t++) {
            int idx = tid + t * 512;            // 0..2047 16B chunks
            int row = idx >> 4;                 // 16 chunks per 256B row
            int c   = idx & 15;
            uint32_t off = (uint32_t)(row * 256) + (uint32_t)((c ^ (row & 7)) << 4);
            *(uint4*)(smem + OFF_A + off) = srcA[idx];
            *(uint4*)(smem + OFF_B + off) = srcB[idx];
        }
        if (tid < 128) {
            ((float*)(smem + OFF_NA))[tid]  = g_norm[nbase + i0 + tid];
            ((float*)(smem + OFF_NB))[tid]  = g_norm[nbase + j0 + tid];
            ((float*)(smem + OFF_RNA))[tid] = g_rnorm[nbase + i0 + tid];
            ((float*)(smem + OFF_RNB))[tid] = g_rnorm[nbase + j0 + tid];
        }
        if (tid == 0) *(int*)(smem + OFF_QCNT) = 0;
    }
    __syncthreads();

    // ---- MMA mainloop: single pass, 8 ksteps of 16, single-buffered ----
    float acc[2][4][4];
#pragma unroll
    for (int mf = 0; mf < 2; mf++)
#pragma unroll
        for (int nf = 0; nf < 4; nf++)
#pragma unroll
            for (int r = 0; r < 4; r++) acc[mf][nf][r] = 0.f;

    const uint32_t abase = sb + OFF_A;
    const uint32_t bbase = sb + OFF_B;

    const int a_row  = warp_m * 32 + (lane & 15);
    const int a_ksel = lane >> 4;
    const int a_swz  = a_row & 7;
    const uint32_t a_rb0 = (uint32_t)(a_row * 256);
    const uint32_t a_rb1 = (uint32_t)((a_row + 16) * 256);
    const int b_row  = warp_n * 32 + (lane & 7) + ((lane >> 4) << 3);
    const int b_ksel = (lane >> 3) & 1;
    const int b_swz  = b_row & 7;
    const uint32_t b_rb0 = (uint32_t)(b_row * 256);
    const uint32_t b_rb1 = (uint32_t)((b_row + 16) * 256);

#pragma unroll
    for (int s = 0; s < 8; s++) {
        uint32_t abuf[2][4], bbuf[2][4];
        uint32_t ac = (uint32_t)((s * 2 + a_ksel) ^ a_swz) << 4;
        uint32_t bc = (uint32_t)((s * 2 + b_ksel) ^ b_swz) << 4;
        ldsm_x4(abuf[0], abase + a_rb0 + ac);
        ldsm_x4(abuf[1], abase + a_rb1 + ac);
        ldsm_x4(bbuf[0], bbase + b_rb0 + bc);
        ldsm_x4(bbuf[1], bbase + b_rb1 + bc);
#pragma unroll
        for (int mf = 0; mf < 2; mf++)
#pragma unroll
            for (int q = 0; q < 2; q++) {
                mma_f16(acc[mf][q * 2 + 0], abuf[mf], &bbuf[q][0]);
                mma_f16(acc[mf][q * 2 + 1], abuf[mf], &bbuf[q][2]);
            }
    }

    // ---- Epilogue: cosine + threshold; direct main + mirror stores ----
    {
        const float* nA  = (const float*)(smem + OFF_NA);
        const float* nB  = (const float*)(smem + OFF_NB);
        const float* rnA = (const float*)(smem + OFF_RNA);
        const float* rnB = (const float*)(smem + OFF_RNB);
        int*   qcnt  = (int*)(smem + OFF_QCNT);
        int*   queue = (int*)(smem + OFF_QUEUE);

#pragma unroll
        for (int mf = 0; mf < 2; mf++) {
            int r_lo = warp_m * 32 + mf * 16 + (lane >> 2);
#pragma unroll
            for (int half = 0; half < 2; half++) {
                int r = r_lo + half * 8;
                float nm = nA[r], rnm = rnA[r];
#pragma unroll
                for (int nf = 0; nf < 4; nf++) {
                    int c0 = warp_n * 32 + nf * 8 + (lane & 3) * 2;
                    float res[2];
#pragma unroll
                    for (int e = 0; e < 2; e++) {
                        int c = c0 + e;
                        float dot = acc[mf][nf][half * 2 + e];
                        float t = nm * nB[c];
                        float f = (t >= COS_EPS) ? (rnm * rnB[c]) : (1.0f / COS_EPS);
                        float v = fabsf(dot) * f;
                        if (fabsf(v - THRESHOLD) < FIX_WIN) {
                            int qi = atomicAdd(qcnt, 1);
                            if (qi < QCAP) queue[qi] = (r << 8) | c;
                        }
                        res[e] = (v > THRESHOLD) ? v : 0.f;
                        if (offdiag)
                            __stcs(outb + (size_t)(j0 + c) * NN + (i0 + r), res[e]);
                    }
                    __stcs((float2*)(outb + (size_t)(i0 + r) * NN + (j0 + c0)),
                           make_float2(res[0], res[1]));
                }
            }
        }
    }
    __syncthreads();   // all approx stores + queue entries visible

    // ---- Drain fixup queue: one warp per entry, exact fp32 dot from g_h ----
    {
        const float* nA = (const float*)(smem + OFF_NA);
        const float* nB = (const float*)(smem + OFF_NB);
        int qn = *(int*)(smem + OFF_QCNT);
        if (qn > QCAP) qn = QCAP;
        const int* queue = (const int*)(smem + OFF_QUEUE);

        for (int q = wid; q < qn; q += 16) {
            int rc = queue[q];
            int r = rc >> 8, c = rc & 255;
            const float4* hi4 = (const float4*)(g_h + hbase + (size_t)(i0 + r) * DOUT);
            const float4* hj4 = (const float4*)(g_h + hbase + (size_t)(j0 + c) * DOUT);
            float4 a = hi4[lane], bb = hj4[lane];
            float d = a.x * bb.x + a.y * bb.y + a.z * bb.z + a.w * bb.w;
#pragma unroll
            for (int off = 16; off > 0; off >>= 1)
                d += __shfl_xor_sync(0xFFFFFFFFu, d, off);
            if (lane == 0) {
                float denom = fmaxf(nA[r] * nB[c], COS_EPS);
                float v = fabsf(d) / denom;
                float res = (v > THRESHOLD) ? v : 0.f;
                __stcs(outb + (size_t)(i0 + r) * NN + (j0 + c), res);     // main
                if (offdiag)
                    __stcs(outb + (size_t)(j0 + c) * NN + (i0 + r), res); // mirror
            }
        }
    }
}

// ---------------------------------------------------------------------------
extern "C" void kernel_launch(void* const* d_in, const int* in_sizes, int n_in,
                              void* d_out, int out_size)
{
    (void)in_sizes; (void)n_in; (void)out_size;
    const float* z = (const float*)d_in[0];
    const float* W = (const float*)d_in[1];
    float* out = (float*)d_out;

    static bool attrs_set = false;
    if (!attrs_set) {
        cudaFuncSetAttribute(gemm1_kernel, cudaFuncAttributeMaxDynamicSharedMemorySize, GEMM1_SMEM);
        cudaFuncSetAttribute(gram_f16_kernel, cudaFuncAttributeMaxDynamicSharedMemorySize, GRAM_SMEM);
        attrs_set = true;
    }

    gemm1_kernel<<<BB * NN / 64, 128, GEMM1_SMEM>>>(z, W);
    dim3 grid(528, BB);
    gram_f16_kernel<<<grid, 512, GRAM_SMEM>>>(out);
}